// round 15
// baseline (speedup 1.0000x reference)
#include <cuda_runtime.h>
#include <cstdint>

// Problem dims (fixed by reference)
#define NB   32
#define H0   512
#define W0   512
#define H1   256
#define W1   256
#define HP   258            // padded H1/W1 (+1 halo each side)
#define H2   128
#define W2   128
#define MPIX (H2*W2)   // 16384
#define K3_CHUNKS 8

// Scratch (device globals: allocation-free)
// g_h1p: NHWC4 with 1-pixel zero halo. Halo is never written -> stays zero
// from static zero-init across all graph replays.
__device__ float g_h1p[(size_t)NB * HP * HP * 4];
__device__ float g_h2[(size_t)NB * MPIX * 16];     // NHWC pixel-major
__device__ float g_part[NB][K3_CHUNKS][68];        // netvlad partials
__device__ int   g_done[NB];                        // zero-init; self-resetting

// ---------------------------------------------------------------------------
// Kernel 1: conv1(3->4, 3x3 SAME) + ReLU + 2x2 avgpool, NCHW -> padded NHWC.
// Smem-staged; 2 pooled outputs per thread; vector LDS. (R8 proven, at floor)
// grid = (H1, NB), block = 128
// ---------------------------------------------------------------------------
#define C1_THREADS 128
__global__ void __launch_bounds__(C1_THREADS) conv1_pool_kernel(
    const float* __restrict__ x,
    const float* __restrict__ w,   // (4,3,3,3)
    const float* __restrict__ b)
{
    __shared__ float  s_in[3][4][516];
    __shared__ float4 sw4[27];
    __shared__ float  sb[4];
    const int tid = threadIdx.x;
    if (tid < 27)
        sw4[tid] = make_float4(w[tid], w[27 + tid], w[54 + tid], w[81 + tid]);
    if (tid < 4) sb[tid] = b[tid];

    const int py = blockIdx.x;
    const int n  = blockIdx.y;
    const int y0 = 2 * py - 1;

    if (tid < 12) {
        const int c = tid >> 2, r = tid & 3;
        s_in[c][r][0]   = 0.0f;
        s_in[c][r][513] = 0.0f;
        s_in[c][r][514] = 0.0f;
        s_in[c][r][515] = 0.0f;
    }

    const float* xn = x + (size_t)n * 3 * H0 * W0;
#pragma unroll
    for (int i = 0; i < 48; ++i) {
        const int idx = tid + i * C1_THREADS;
        const int col = idx & 511;
        const int r   = (idx >> 9) & 3;
        const int c   = idx >> 11;
        const int y   = y0 + r;
        const float v = ((unsigned)y < (unsigned)H0)
                            ? __ldg(xn + (size_t)c * H0 * W0 + (size_t)y * W0 + col)
                            : 0.0f;
        s_in[c][r][1 + col] = v;
    }
    __syncthreads();

    float a00[4], a01[4], a10[4], a11[4];
    float b00[4], b01[4], b10[4], b11[4];
#pragma unroll
    for (int co = 0; co < 4; ++co) {
        const float bb = sb[co];
        a00[co] = bb; a01[co] = bb; a10[co] = bb; a11[co] = bb;
        b00[co] = bb; b01[co] = bb; b10[co] = bb; b11[co] = bb;
    }

    const int base = 4 * tid;
#pragma unroll
    for (int c = 0; c < 3; ++c) {
        float p[4][6];
#pragma unroll
        for (int dy = 0; dy < 4; ++dy) {
            const float4 q  = *(const float4*)&s_in[c][dy][base];
            const float2 q2 = *(const float2*)&s_in[c][dy][base + 4];
            p[dy][0] = q.x;  p[dy][1] = q.y;  p[dy][2] = q.z;
            p[dy][3] = q.w;  p[dy][4] = q2.x; p[dy][5] = q2.y;
        }
#pragma unroll
        for (int ky = 0; ky < 3; ++ky)
#pragma unroll
            for (int kx = 0; kx < 3; ++kx) {
                const float4 w4 = sw4[c * 9 + ky * 3 + kx];
                const float t00 = p[ky    ][kx    ];
                const float t01 = p[ky    ][kx + 1];
                const float t10 = p[ky + 1][kx    ];
                const float t11 = p[ky + 1][kx + 1];
                const float u00 = p[ky    ][kx + 2];
                const float u01 = p[ky    ][kx + 3];
                const float u10 = p[ky + 1][kx + 2];
                const float u11 = p[ky + 1][kx + 3];
                a00[0] = fmaf(t00, w4.x, a00[0]); a00[1] = fmaf(t00, w4.y, a00[1]);
                a00[2] = fmaf(t00, w4.z, a00[2]); a00[3] = fmaf(t00, w4.w, a00[3]);
                a01[0] = fmaf(t01, w4.x, a01[0]); a01[1] = fmaf(t01, w4.y, a01[1]);
                a01[2] = fmaf(t01, w4.z, a01[2]); a01[3] = fmaf(t01, w4.w, a01[3]);
                a10[0] = fmaf(t10, w4.x, a10[0]); a10[1] = fmaf(t10, w4.y, a10[1]);
                a10[2] = fmaf(t10, w4.z, a10[2]); a10[3] = fmaf(t10, w4.w, a10[3]);
                a11[0] = fmaf(t11, w4.x, a11[0]); a11[1] = fmaf(t11, w4.y, a11[1]);
                a11[2] = fmaf(t11, w4.z, a11[2]); a11[3] = fmaf(t11, w4.w, a11[3]);
                b00[0] = fmaf(u00, w4.x, b00[0]); b00[1] = fmaf(u00, w4.y, b00[1]);
                b00[2] = fmaf(u00, w4.z, b00[2]); b00[3] = fmaf(u00, w4.w, b00[3]);
                b01[0] = fmaf(u01, w4.x, b01[0]); b01[1] = fmaf(u01, w4.y, b01[1]);
                b01[2] = fmaf(u01, w4.z, b01[2]); b01[3] = fmaf(u01, w4.w, b01[3]);
                b10[0] = fmaf(u10, w4.x, b10[0]); b10[1] = fmaf(u10, w4.y, b10[1]);
                b10[2] = fmaf(u10, w4.z, b10[2]); b10[3] = fmaf(u10, w4.w, b10[3]);
                b11[0] = fmaf(u11, w4.x, b11[0]); b11[1] = fmaf(u11, w4.y, b11[1]);
                b11[2] = fmaf(u11, w4.z, b11[2]); b11[3] = fmaf(u11, w4.w, b11[3]);
            }
    }

    float r0[4], r1[4];
#pragma unroll
    for (int co = 0; co < 4; ++co) {
        r0[co] = 0.25f * (fmaxf(a00[co], 0.f) + fmaxf(a01[co], 0.f) +
                          fmaxf(a10[co], 0.f) + fmaxf(a11[co], 0.f));
        r1[co] = 0.25f * (fmaxf(b00[co], 0.f) + fmaxf(b01[co], 0.f) +
                          fmaxf(b10[co], 0.f) + fmaxf(b11[co], 0.f));
    }
    // padded store: output (py, 2t) -> padded (py+1, 2t+1)
    float* o = g_h1p + ((size_t)n * HP * HP + (size_t)(py + 1) * HP + (2 * tid + 1)) * 4;
    ((float4*)o)[0] = make_float4(r0[0], r0[1], r0[2], r0[3]);
    ((float4*)o)[1] = make_float4(r1[0], r1[1], r1[2], r1[3]);
}

// ---------------------------------------------------------------------------
// Kernel 2: conv2 via Winograd F(2x2,3x3) + ReLU + 2x2 avgpool.
// Branch-free loads from halo-padded g_h1p. 2 co per group (float2 U).
// grid = (H2, NB), block = 128
// ---------------------------------------------------------------------------
__global__ void __launch_bounds__(W2) conv2_wino_kernel(
    const float* __restrict__ w,   // (16,4,3,3)
    const float* __restrict__ b)
{
    __shared__ float sU[16 * 4 * 16];   // [pos(16)][ci(4)][co(16)]
    __shared__ float sb[16];
    const int tid = threadIdx.x;
    if (tid < 16) sb[tid] = b[tid];

    // U = G g G^T for all (co,ci); 64 threads, one pair each
    if (tid < 64) {
        const int ci = tid >> 4, co = tid & 15;
        float g[3][3];
#pragma unroll
        for (int r = 0; r < 3; ++r)
#pragma unroll
            for (int c = 0; c < 3; ++c)
                g[r][c] = __ldg(w + co * 36 + ci * 9 + r * 3 + c);
        float T[4][3];
#pragma unroll
        for (int c = 0; c < 3; ++c) {
            T[0][c] = g[0][c];
            T[1][c] = 0.5f * (g[0][c] + g[1][c] + g[2][c]);
            T[2][c] = 0.5f * (g[0][c] - g[1][c] + g[2][c]);
            T[3][c] = g[2][c];
        }
#pragma unroll
        for (int r = 0; r < 4; ++r) {
            float U0 = T[r][0];
            float U1 = 0.5f * (T[r][0] + T[r][1] + T[r][2]);
            float U2 = 0.5f * (T[r][0] - T[r][1] + T[r][2]);
            float U3 = T[r][2];
            sU[((r * 4 + 0) * 4 + ci) * 16 + co] = U0;
            sU[((r * 4 + 1) * 4 + ci) * 16 + co] = U1;
            sU[((r * 4 + 2) * 4 + ci) * 16 + co] = U2;
            sU[((r * 4 + 3) * 4 + ci) * 16 + co] = U3;
        }
    }
    __syncthreads();

    const int px = tid;
    const int py = blockIdx.x;
    const int n  = blockIdx.y;

    // conv input rows y0+dy = 2py-1+dy -> padded rows 2py+dy; cols -> 2px+dx.
    // Halo is zero => same SAME-padding semantics, no guards.
    const float* bp = g_h1p + ((size_t)n * HP * HP + (size_t)(2 * py) * HP + 2 * px) * 4;
    float p[4][4][4];  // [dy][dx][ci]
#pragma unroll
    for (int dy = 0; dy < 4; ++dy)
#pragma unroll
        for (int dx = 0; dx < 4; ++dx) {
            const float4 t = *(const float4*)(bp + ((size_t)dy * HP + dx) * 4);
            p[dy][dx][0] = t.x; p[dy][dx][1] = t.y;
            p[dy][dx][2] = t.z; p[dy][dx][3] = t.w;
        }

    // V = B^T d B per ci
    float V[4][16];   // [ci][pos]
#pragma unroll
    for (int ci = 0; ci < 4; ++ci) {
        float t[4][4];
#pragma unroll
        for (int c = 0; c < 4; ++c) {
            t[0][c] = p[0][c][ci] - p[2][c][ci];
            t[1][c] = p[1][c][ci] + p[2][c][ci];
            t[2][c] = p[2][c][ci] - p[1][c][ci];
            t[3][c] = p[1][c][ci] - p[3][c][ci];
        }
#pragma unroll
        for (int r = 0; r < 4; ++r) {
            V[ci][r * 4 + 0] = t[r][0] - t[r][2];
            V[ci][r * 4 + 1] = t[r][1] + t[r][2];
            V[ci][r * 4 + 2] = t[r][2] - t[r][1];
            V[ci][r * 4 + 3] = t[r][1] - t[r][3];
        }
    }

    // elementwise + output transform, 2 output channels at a time
    float res[16];
#pragma unroll
    for (int grp = 0; grp < 8; ++grp) {
        float Ma[16], Mb[16];
#pragma unroll
        for (int i = 0; i < 16; ++i) { Ma[i] = 0.f; Mb[i] = 0.f; }
#pragma unroll
        for (int pos = 0; pos < 16; ++pos)
#pragma unroll
            for (int ci = 0; ci < 4; ++ci) {
                const float2 u = *(const float2*)&sU[(pos * 4 + ci) * 16 + 2 * grp];
                Ma[pos] = fmaf(u.x, V[ci][pos], Ma[pos]);
                Mb[pos] = fmaf(u.y, V[ci][pos], Mb[pos]);
            }
        const float ba = sb[2 * grp], bbv = sb[2 * grp + 1];
        {
            float s0[4], s1[4];
#pragma unroll
            for (int c = 0; c < 4; ++c) {
                s0[c] = Ma[c] + Ma[4 + c] + Ma[8 + c];
                s1[c] = Ma[4 + c] - Ma[8 + c] - Ma[12 + c];
            }
            const float Y00 = s0[0] + s0[1] + s0[2];
            const float Y01 = s0[1] - s0[2] - s0[3];
            const float Y10 = s1[0] + s1[1] + s1[2];
            const float Y11 = s1[1] - s1[2] - s1[3];
            res[2 * grp] = 0.25f * (fmaxf(Y00 + ba, 0.f) + fmaxf(Y01 + ba, 0.f) +
                                    fmaxf(Y10 + ba, 0.f) + fmaxf(Y11 + ba, 0.f));
        }
        {
            float s0[4], s1[4];
#pragma unroll
            for (int c = 0; c < 4; ++c) {
                s0[c] = Mb[c] + Mb[4 + c] + Mb[8 + c];
                s1[c] = Mb[4 + c] - Mb[8 + c] - Mb[12 + c];
            }
            const float Y00 = s0[0] + s0[1] + s0[2];
            const float Y01 = s0[1] - s0[2] - s0[3];
            const float Y10 = s1[0] + s1[1] + s1[2];
            const float Y11 = s1[1] - s1[2] - s1[3];
            res[2 * grp + 1] = 0.25f * (fmaxf(Y00 + bbv, 0.f) + fmaxf(Y01 + bbv, 0.f) +
                                        fmaxf(Y10 + bbv, 0.f) + fmaxf(Y11 + bbv, 0.f));
        }
    }

    float4* o4 = (float4*)(g_h2 + ((size_t)n * MPIX + (size_t)py * W2 + px) * 16);
#pragma unroll
    for (int q = 0; q < 4; ++q)
        o4[q] = make_float4(res[q*4+0], res[q*4+1], res[q*4+2], res[q*4+3]);
}

// ---------------------------------------------------------------------------
// Kernel 3: NetVLAD partials + last-block finalize.
// grid=(NB, K3_CHUNKS), block=64 (32 px/thread; reduction overhead halved)
// ---------------------------------------------------------------------------
#define K3A_THREADS 64
__global__ void __launch_bounds__(K3A_THREADS) netvlad_fused_kernel(
    const float* __restrict__ aw, const float* __restrict__ ab,
    const float* __restrict__ cent,
    const float* __restrict__ lw, const float* __restrict__ lb,
    float* __restrict__ out)
{
    const int n   = blockIdx.x;
    const int ch  = blockIdx.y;
    const int tid = threadIdx.x;
    const int lane = tid & 31;
    const int wrp  = tid >> 5;

    __shared__ float s_aw[64];
    __shared__ float s_ab[4];
    if (tid < 64) s_aw[tid] = aw[tid];
    if (tid < 4)  s_ab[tid] = ab[tid];
    __syncthreads();

    float acc[68];
#pragma unroll
    for (int i = 0; i < 68; ++i) acc[i] = 0.0f;

    const int m0 = ch * (MPIX / K3_CHUNKS);
    const int m1 = m0 + (MPIX / K3_CHUNKS);
    const float* base = g_h2 + (size_t)n * MPIX * 16;
    for (int m = m0 + tid; m < m1; m += K3A_THREADS) {
        const float4* xp = (const float4*)(base + (size_t)m * 16);
        float xv[16];
#pragma unroll
        for (int q = 0; q < 4; ++q) {
            float4 v = xp[q];
            xv[q*4+0] = v.x; xv[q*4+1] = v.y; xv[q*4+2] = v.z; xv[q*4+3] = v.w;
        }
        float lg[4];
#pragma unroll
        for (int k = 0; k < 4; ++k) {
            float sres = s_ab[k];
#pragma unroll
            for (int c = 0; c < 16; ++c) sres = fmaf(xv[c], s_aw[k * 16 + c], sres);
            lg[k] = sres;
        }
        const float mx = fmaxf(fmaxf(lg[0], lg[1]), fmaxf(lg[2], lg[3]));
        float e[4], es = 0.0f;
#pragma unroll
        for (int k = 0; k < 4; ++k) { e[k] = __expf(lg[k] - mx); es += e[k]; }
        const float inv = __fdividef(1.0f, es);
#pragma unroll
        for (int k = 0; k < 4; ++k) {
            const float a = e[k] * inv;
            acc[64 + k] += a;
#pragma unroll
            for (int c = 0; c < 16; ++c)
                acc[k * 16 + c] = fmaf(a, xv[c], acc[k * 16 + c]);
        }
    }

#pragma unroll
    for (int off = 16; off > 0; off >>= 1)
#pragma unroll
        for (int i = 0; i < 68; ++i)
            acc[i] += __shfl_down_sync(0xffffffffu, acc[i], off);

    __shared__ float red[K3A_THREADS / 32][68];
    if (lane == 0)
#pragma unroll
        for (int i = 0; i < 68; ++i) red[wrp][i] = acc[i];
    __syncthreads();
    for (int i = tid; i < 68; i += K3A_THREADS) {
        float sres = 0.0f;
#pragma unroll
        for (int ww = 0; ww < K3A_THREADS / 32; ++ww) sres += red[ww][i];
        g_part[n][ch][i] = sres;
    }

    // ---- last-block-per-image finalize (store -> fence -> sync -> atomic) --
    __threadfence();
    __syncthreads();
    __shared__ int s_last;
    if (tid == 0) {
        const int old = atomicAdd(&g_done[n], 1);
        s_last = (old == K3_CHUNKS - 1) ? 1 : 0;
    }
    __syncthreads();
    if (!s_last) return;

    __shared__ float sv[68];
    for (int i = tid; i < 68; i += K3A_THREADS) {
        float sres = 0.0f;
#pragma unroll
        for (int cc = 0; cc < K3_CHUNKS; ++cc) sres += __ldcg(&g_part[n][cc][i]);
        sv[i] = sres;
    }
    __syncthreads();

    __shared__ float v2[64];
    __shared__ float nk[4];
    __shared__ float gn;
    if (tid < 64) {
        const int k = tid >> 4;
        v2[tid] = sv[tid] - sv[64 + k] * __ldg(cent + tid);
    }
    __syncthreads();
    if (tid < 4) {
        float sres = 0.0f;
#pragma unroll
        for (int c = 0; c < 16; ++c) { const float v = v2[tid * 16 + c]; sres = fmaf(v, v, sres); }
        nk[tid] = fmaxf(sqrtf(sres), 1e-12f);
    }
    __syncthreads();
    if (tid < 64) v2[tid] = v2[tid] / nk[tid >> 4];
    __syncthreads();
    if (tid == 0) {
        float sres = 0.0f;
#pragma unroll
        for (int i = 0; i < 64; ++i) sres = fmaf(v2[i], v2[i], sres);
        gn = fmaxf(sqrtf(sres), 1e-12f);
        g_done[n] = 0;   // reset for next graph replay
    }
    __syncthreads();
    if (tid < 7) {
        float sres = __ldg(lb + tid);
        const float ig = 1.0f / gn;
#pragma unroll
        for (int i = 0; i < 64; ++i)
            sres = fmaf(v2[i] * ig, __ldg(lw + tid * 64 + i), sres);
        out[n * 7 + tid] = sres;
    }
}

// ---------------------------------------------------------------------------
extern "C" void kernel_launch(void* const* d_in, const int* in_sizes, int n_in,
                              void* d_out, int out_size)
{
    (void)in_sizes; (void)n_in; (void)out_size;
    const float* x       = (const float*)d_in[0];
    const float* conv1_w = (const float*)d_in[1];
    const float* conv1_b = (const float*)d_in[2];
    const float* conv2_w = (const float*)d_in[3];
    const float* conv2_b = (const float*)d_in[4];
    const float* cent    = (const float*)d_in[5];
    const float* aw      = (const float*)d_in[6];
    const float* ab      = (const float*)d_in[7];
    const float* lw      = (const float*)d_in[8];
    const float* lb      = (const float*)d_in[9];
    float* out = (float*)d_out;

    dim3 g1(H1, NB); conv1_pool_kernel<<<g1, C1_THREADS>>>(x, conv1_w, conv1_b);
    dim3 g2(H2, NB); conv2_wino_kernel<<<g2, W2>>>(conv2_w, conv2_b);
    dim3 g3(NB, K3_CHUNKS);
    netvlad_fused_kernel<<<g3, K3A_THREADS>>>(aw, ab, cent, lw, lb, out);
}

// round 16
// speedup vs baseline: 1.0429x; 1.0429x over previous
#include <cuda_runtime.h>
#include <cstdint>

// Problem dims (fixed by reference)
#define NB   32
#define H0   512
#define W0   512
#define H1   256
#define W1   256
#define HP   258            // padded H1/W1 (+1 halo each side)
#define H2   128
#define W2   128
#define MPIX (H2*W2)   // 16384
#define K3_CHUNKS 8

// Scratch (device globals: allocation-free)
// g_h1p: NHWC4 with 1-pixel zero halo. Halo is never written -> stays zero
// from static zero-init across all graph replays.
__device__ float g_h1p[(size_t)NB * HP * HP * 4];
__device__ float g_h2[(size_t)NB * MPIX * 16];     // NHWC pixel-major
__device__ float g_part[NB][K3_CHUNKS][68];        // netvlad partials
__device__ int   g_done[NB];                        // zero-init; self-resetting

// ---------------------------------------------------------------------------
// Kernel 1: conv1(3->4, 3x3 SAME) + ReLU + 2x2 avgpool, NCHW -> padded NHWC.
// Smem-staged; 2 pooled outputs per thread; vector LDS. (R15 measured 54.4us)
// grid = (H1, NB), block = 128
// ---------------------------------------------------------------------------
#define C1_THREADS 128
__global__ void __launch_bounds__(C1_THREADS) conv1_pool_kernel(
    const float* __restrict__ x,
    const float* __restrict__ w,   // (4,3,3,3)
    const float* __restrict__ b)
{
    __shared__ float  s_in[3][4][516];
    __shared__ float4 sw4[27];
    __shared__ float  sb[4];
    const int tid = threadIdx.x;
    if (tid < 27)
        sw4[tid] = make_float4(w[tid], w[27 + tid], w[54 + tid], w[81 + tid]);
    if (tid < 4) sb[tid] = b[tid];

    const int py = blockIdx.x;
    const int n  = blockIdx.y;
    const int y0 = 2 * py - 1;

    if (tid < 12) {
        const int c = tid >> 2, r = tid & 3;
        s_in[c][r][0]   = 0.0f;
        s_in[c][r][513] = 0.0f;
        s_in[c][r][514] = 0.0f;
        s_in[c][r][515] = 0.0f;
    }

    const float* xn = x + (size_t)n * 3 * H0 * W0;
#pragma unroll
    for (int i = 0; i < 48; ++i) {
        const int idx = tid + i * C1_THREADS;
        const int col = idx & 511;
        const int r   = (idx >> 9) & 3;
        const int c   = idx >> 11;
        const int y   = y0 + r;
        const float v = ((unsigned)y < (unsigned)H0)
                            ? __ldg(xn + (size_t)c * H0 * W0 + (size_t)y * W0 + col)
                            : 0.0f;
        s_in[c][r][1 + col] = v;
    }
    __syncthreads();

    float a00[4], a01[4], a10[4], a11[4];
    float b00[4], b01[4], b10[4], b11[4];
#pragma unroll
    for (int co = 0; co < 4; ++co) {
        const float bb = sb[co];
        a00[co] = bb; a01[co] = bb; a10[co] = bb; a11[co] = bb;
        b00[co] = bb; b01[co] = bb; b10[co] = bb; b11[co] = bb;
    }

    const int base = 4 * tid;
#pragma unroll
    for (int c = 0; c < 3; ++c) {
        float p[4][6];
#pragma unroll
        for (int dy = 0; dy < 4; ++dy) {
            const float4 q  = *(const float4*)&s_in[c][dy][base];
            const float2 q2 = *(const float2*)&s_in[c][dy][base + 4];
            p[dy][0] = q.x;  p[dy][1] = q.y;  p[dy][2] = q.z;
            p[dy][3] = q.w;  p[dy][4] = q2.x; p[dy][5] = q2.y;
        }
#pragma unroll
        for (int ky = 0; ky < 3; ++ky)
#pragma unroll
            for (int kx = 0; kx < 3; ++kx) {
                const float4 w4 = sw4[c * 9 + ky * 3 + kx];
                const float t00 = p[ky    ][kx    ];
                const float t01 = p[ky    ][kx + 1];
                const float t10 = p[ky + 1][kx    ];
                const float t11 = p[ky + 1][kx + 1];
                const float u00 = p[ky    ][kx + 2];
                const float u01 = p[ky    ][kx + 3];
                const float u10 = p[ky + 1][kx + 2];
                const float u11 = p[ky + 1][kx + 3];
                a00[0] = fmaf(t00, w4.x, a00[0]); a00[1] = fmaf(t00, w4.y, a00[1]);
                a00[2] = fmaf(t00, w4.z, a00[2]); a00[3] = fmaf(t00, w4.w, a00[3]);
                a01[0] = fmaf(t01, w4.x, a01[0]); a01[1] = fmaf(t01, w4.y, a01[1]);
                a01[2] = fmaf(t01, w4.z, a01[2]); a01[3] = fmaf(t01, w4.w, a01[3]);
                a10[0] = fmaf(t10, w4.x, a10[0]); a10[1] = fmaf(t10, w4.y, a10[1]);
                a10[2] = fmaf(t10, w4.z, a10[2]); a10[3] = fmaf(t10, w4.w, a10[3]);
                a11[0] = fmaf(t11, w4.x, a11[0]); a11[1] = fmaf(t11, w4.y, a11[1]);
                a11[2] = fmaf(t11, w4.z, a11[2]); a11[3] = fmaf(t11, w4.w, a11[3]);
                b00[0] = fmaf(u00, w4.x, b00[0]); b00[1] = fmaf(u00, w4.y, b00[1]);
                b00[2] = fmaf(u00, w4.z, b00[2]); b00[3] = fmaf(u00, w4.w, b00[3]);
                b01[0] = fmaf(u01, w4.x, b01[0]); b01[1] = fmaf(u01, w4.y, b01[1]);
                b01[2] = fmaf(u01, w4.z, b01[2]); b01[3] = fmaf(u01, w4.w, b01[3]);
                b10[0] = fmaf(u10, w4.x, b10[0]); b10[1] = fmaf(u10, w4.y, b10[1]);
                b10[2] = fmaf(u10, w4.z, b10[2]); b10[3] = fmaf(u10, w4.w, b10[3]);
                b11[0] = fmaf(u11, w4.x, b11[0]); b11[1] = fmaf(u11, w4.y, b11[1]);
                b11[2] = fmaf(u11, w4.z, b11[2]); b11[3] = fmaf(u11, w4.w, b11[3]);
            }
    }

    float r0[4], r1[4];
#pragma unroll
    for (int co = 0; co < 4; ++co) {
        r0[co] = 0.25f * (fmaxf(a00[co], 0.f) + fmaxf(a01[co], 0.f) +
                          fmaxf(a10[co], 0.f) + fmaxf(a11[co], 0.f));
        r1[co] = 0.25f * (fmaxf(b00[co], 0.f) + fmaxf(b01[co], 0.f) +
                          fmaxf(b10[co], 0.f) + fmaxf(b11[co], 0.f));
    }
    // padded store: output (py, 2t) -> padded (py+1, 2t+1)
    float* o = g_h1p + ((size_t)n * HP * HP + (size_t)(py + 1) * HP + (2 * tid + 1)) * 4;
    ((float4*)o)[0] = make_float4(r0[0], r0[1], r0[2], r0[3]);
    ((float4*)o)[1] = make_float4(r1[0], r1[1], r1[2], r1[3]);
}

// ---------------------------------------------------------------------------
// Kernel 2: conv2 via Winograd F(2x2,3x3) + ReLU + 2x2 avgpool.
// Branch-free loads from halo-padded g_h1p. 2 co per group (float2 U).
// grid = (H2, NB), block = 128
// ---------------------------------------------------------------------------
__global__ void __launch_bounds__(W2) conv2_wino_kernel(
    const float* __restrict__ w,   // (16,4,3,3)
    const float* __restrict__ b)
{
    __shared__ float sU[16 * 4 * 16];   // [pos(16)][ci(4)][co(16)]
    __shared__ float sb[16];
    const int tid = threadIdx.x;
    if (tid < 16) sb[tid] = b[tid];

    // U = G g G^T for all (co,ci); 64 threads, one pair each
    if (tid < 64) {
        const int ci = tid >> 4, co = tid & 15;
        float g[3][3];
#pragma unroll
        for (int r = 0; r < 3; ++r)
#pragma unroll
            for (int c = 0; c < 3; ++c)
                g[r][c] = __ldg(w + co * 36 + ci * 9 + r * 3 + c);
        float T[4][3];
#pragma unroll
        for (int c = 0; c < 3; ++c) {
            T[0][c] = g[0][c];
            T[1][c] = 0.5f * (g[0][c] + g[1][c] + g[2][c]);
            T[2][c] = 0.5f * (g[0][c] - g[1][c] + g[2][c]);
            T[3][c] = g[2][c];
        }
#pragma unroll
        for (int r = 0; r < 4; ++r) {
            float U0 = T[r][0];
            float U1 = 0.5f * (T[r][0] + T[r][1] + T[r][2]);
            float U2 = 0.5f * (T[r][0] - T[r][1] + T[r][2]);
            float U3 = T[r][2];
            sU[((r * 4 + 0) * 4 + ci) * 16 + co] = U0;
            sU[((r * 4 + 1) * 4 + ci) * 16 + co] = U1;
            sU[((r * 4 + 2) * 4 + ci) * 16 + co] = U2;
            sU[((r * 4 + 3) * 4 + ci) * 16 + co] = U3;
        }
    }
    __syncthreads();

    const int px = tid;
    const int py = blockIdx.x;
    const int n  = blockIdx.y;

    // conv input rows y0+dy = 2py-1+dy -> padded rows 2py+dy; cols -> 2px+dx.
    // Halo is zero => same SAME-padding semantics, no guards.
    const float* bp = g_h1p + ((size_t)n * HP * HP + (size_t)(2 * py) * HP + 2 * px) * 4;
    float p[4][4][4];  // [dy][dx][ci]
#pragma unroll
    for (int dy = 0; dy < 4; ++dy)
#pragma unroll
        for (int dx = 0; dx < 4; ++dx) {
            const float4 t = *(const float4*)(bp + ((size_t)dy * HP + dx) * 4);
            p[dy][dx][0] = t.x; p[dy][dx][1] = t.y;
            p[dy][dx][2] = t.z; p[dy][dx][3] = t.w;
        }

    // V = B^T d B per ci
    float V[4][16];   // [ci][pos]
#pragma unroll
    for (int ci = 0; ci < 4; ++ci) {
        float t[4][4];
#pragma unroll
        for (int c = 0; c < 4; ++c) {
            t[0][c] = p[0][c][ci] - p[2][c][ci];
            t[1][c] = p[1][c][ci] + p[2][c][ci];
            t[2][c] = p[2][c][ci] - p[1][c][ci];
            t[3][c] = p[1][c][ci] - p[3][c][ci];
        }
#pragma unroll
        for (int r = 0; r < 4; ++r) {
            V[ci][r * 4 + 0] = t[r][0] - t[r][2];
            V[ci][r * 4 + 1] = t[r][1] + t[r][2];
            V[ci][r * 4 + 2] = t[r][2] - t[r][1];
            V[ci][r * 4 + 3] = t[r][1] - t[r][3];
        }
    }

    // elementwise + output transform, 2 output channels at a time
    float res[16];
#pragma unroll
    for (int grp = 0; grp < 8; ++grp) {
        float Ma[16], Mb[16];
#pragma unroll
        for (int i = 0; i < 16; ++i) { Ma[i] = 0.f; Mb[i] = 0.f; }
#pragma unroll
        for (int pos = 0; pos < 16; ++pos)
#pragma unroll
            for (int ci = 0; ci < 4; ++ci) {
                const float2 u = *(const float2*)&sU[(pos * 4 + ci) * 16 + 2 * grp];
                Ma[pos] = fmaf(u.x, V[ci][pos], Ma[pos]);
                Mb[pos] = fmaf(u.y, V[ci][pos], Mb[pos]);
            }
        const float ba = sb[2 * grp], bbv = sb[2 * grp + 1];
        {
            float s0[4], s1[4];
#pragma unroll
            for (int c = 0; c < 4; ++c) {
                s0[c] = Ma[c] + Ma[4 + c] + Ma[8 + c];
                s1[c] = Ma[4 + c] - Ma[8 + c] - Ma[12 + c];
            }
            const float Y00 = s0[0] + s0[1] + s0[2];
            const float Y01 = s0[1] - s0[2] - s0[3];
            const float Y10 = s1[0] + s1[1] + s1[2];
            const float Y11 = s1[1] - s1[2] - s1[3];
            res[2 * grp] = 0.25f * (fmaxf(Y00 + ba, 0.f) + fmaxf(Y01 + ba, 0.f) +
                                    fmaxf(Y10 + ba, 0.f) + fmaxf(Y11 + ba, 0.f));
        }
        {
            float s0[4], s1[4];
#pragma unroll
            for (int c = 0; c < 4; ++c) {
                s0[c] = Mb[c] + Mb[4 + c] + Mb[8 + c];
                s1[c] = Mb[4 + c] - Mb[8 + c] - Mb[12 + c];
            }
            const float Y00 = s0[0] + s0[1] + s0[2];
            const float Y01 = s0[1] - s0[2] - s0[3];
            const float Y10 = s1[0] + s1[1] + s1[2];
            const float Y11 = s1[1] - s1[2] - s1[3];
            res[2 * grp + 1] = 0.25f * (fmaxf(Y00 + bbv, 0.f) + fmaxf(Y01 + bbv, 0.f) +
                                        fmaxf(Y10 + bbv, 0.f) + fmaxf(Y11 + bbv, 0.f));
        }
    }

    float4* o4 = (float4*)(g_h2 + ((size_t)n * MPIX + (size_t)py * W2 + px) * 16);
#pragma unroll
    for (int q = 0; q < 4; ++q)
        o4[q] = make_float4(res[q*4+0], res[q*4+1], res[q*4+2], res[q*4+3]);
}

// ---------------------------------------------------------------------------
// Kernel 3: NetVLAD partials + last-block finalize.
// grid=(NB, K3_CHUNKS), block=128 (R13 proven sweet spot)
// ---------------------------------------------------------------------------
#define K3A_THREADS 128
__global__ void __launch_bounds__(K3A_THREADS) netvlad_fused_kernel(
    const float* __restrict__ aw, const float* __restrict__ ab,
    const float* __restrict__ cent,
    const float* __restrict__ lw, const float* __restrict__ lb,
    float* __restrict__ out)
{
    const int n   = blockIdx.x;
    const int ch  = blockIdx.y;
    const int tid = threadIdx.x;
    const int lane = tid & 31;
    const int wrp  = tid >> 5;

    __shared__ float s_aw[64];
    __shared__ float s_ab[4];
    if (tid < 64) s_aw[tid] = aw[tid];
    if (tid < 4)  s_ab[tid] = ab[tid];
    __syncthreads();

    float acc[68];
#pragma unroll
    for (int i = 0; i < 68; ++i) acc[i] = 0.0f;

    const int m0 = ch * (MPIX / K3_CHUNKS);
    const int m1 = m0 + (MPIX / K3_CHUNKS);
    const float* base = g_h2 + (size_t)n * MPIX * 16;
    for (int m = m0 + tid; m < m1; m += K3A_THREADS) {
        const float4* xp = (const float4*)(base + (size_t)m * 16);
        float xv[16];
#pragma unroll
        for (int q = 0; q < 4; ++q) {
            float4 v = xp[q];
            xv[q*4+0] = v.x; xv[q*4+1] = v.y; xv[q*4+2] = v.z; xv[q*4+3] = v.w;
        }
        float lg[4];
#pragma unroll
        for (int k = 0; k < 4; ++k) {
            float sres = s_ab[k];
#pragma unroll
            for (int c = 0; c < 16; ++c) sres = fmaf(xv[c], s_aw[k * 16 + c], sres);
            lg[k] = sres;
        }
        const float mx = fmaxf(fmaxf(lg[0], lg[1]), fmaxf(lg[2], lg[3]));
        float e[4], es = 0.0f;
#pragma unroll
        for (int k = 0; k < 4; ++k) { e[k] = __expf(lg[k] - mx); es += e[k]; }
        const float inv = __fdividef(1.0f, es);
#pragma unroll
        for (int k = 0; k < 4; ++k) {
            const float a = e[k] * inv;
            acc[64 + k] += a;
#pragma unroll
            for (int c = 0; c < 16; ++c)
                acc[k * 16 + c] = fmaf(a, xv[c], acc[k * 16 + c]);
        }
    }

#pragma unroll
    for (int off = 16; off > 0; off >>= 1)
#pragma unroll
        for (int i = 0; i < 68; ++i)
            acc[i] += __shfl_down_sync(0xffffffffu, acc[i], off);

    __shared__ float red[K3A_THREADS / 32][68];
    if (lane == 0)
#pragma unroll
        for (int i = 0; i < 68; ++i) red[wrp][i] = acc[i];
    __syncthreads();
    for (int i = tid; i < 68; i += K3A_THREADS) {
        float sres = 0.0f;
#pragma unroll
        for (int ww = 0; ww < K3A_THREADS / 32; ++ww) sres += red[ww][i];
        g_part[n][ch][i] = sres;
    }

    // ---- last-block-per-image finalize (store -> fence -> sync -> atomic) --
    __threadfence();
    __syncthreads();
    __shared__ int s_last;
    if (tid == 0) {
        const int old = atomicAdd(&g_done[n], 1);
        s_last = (old == K3_CHUNKS - 1) ? 1 : 0;
    }
    __syncthreads();
    if (!s_last) return;

    __shared__ float sv[68];
    for (int i = tid; i < 68; i += K3A_THREADS) {
        float sres = 0.0f;
#pragma unroll
        for (int cc = 0; cc < K3_CHUNKS; ++cc) sres += __ldcg(&g_part[n][cc][i]);
        sv[i] = sres;
    }
    __syncthreads();

    __shared__ float v2[64];
    __shared__ float nk[4];
    __shared__ float gn;
    if (tid < 64) {
        const int k = tid >> 4;
        v2[tid] = sv[tid] - sv[64 + k] * __ldg(cent + tid);
    }
    __syncthreads();
    if (tid < 4) {
        float sres = 0.0f;
#pragma unroll
        for (int c = 0; c < 16; ++c) { const float v = v2[tid * 16 + c]; sres = fmaf(v, v, sres); }
        nk[tid] = fmaxf(sqrtf(sres), 1e-12f);
    }
    __syncthreads();
    if (tid < 64) v2[tid] = v2[tid] / nk[tid >> 4];
    __syncthreads();
    if (tid == 0) {
        float sres = 0.0f;
#pragma unroll
        for (int i = 0; i < 64; ++i) sres = fmaf(v2[i], v2[i], sres);
        gn = fmaxf(sqrtf(sres), 1e-12f);
        g_done[n] = 0;   // reset for next graph replay
    }
    __syncthreads();
    if (tid < 7) {
        float sres = __ldg(lb + tid);
        const float ig = 1.0f / gn;
#pragma unroll
        for (int i = 0; i < 64; ++i)
            sres = fmaf(v2[i] * ig, __ldg(lw + tid * 64 + i), sres);
        out[n * 7 + tid] = sres;
    }
}

// ---------------------------------------------------------------------------
extern "C" void kernel_launch(void* const* d_in, const int* in_sizes, int n_in,
                              void* d_out, int out_size)
{
    (void)in_sizes; (void)n_in; (void)out_size;
    const float* x       = (const float*)d_in[0];
    const float* conv1_w = (const float*)d_in[1];
    const float* conv1_b = (const float*)d_in[2];
    const float* conv2_w = (const float*)d_in[3];
    const float* conv2_b = (const float*)d_in[4];
    const float* cent    = (const float*)d_in[5];
    const float* aw      = (const float*)d_in[6];
    const float* ab      = (const float*)d_in[7];
    const float* lw      = (const float*)d_in[8];
    const float* lb      = (const float*)d_in[9];
    float* out = (float*)d_out;

    dim3 g1(H1, NB); conv1_pool_kernel<<<g1, C1_THREADS>>>(x, conv1_w, conv1_b);
    dim3 g2(H2, NB); conv2_wino_kernel<<<g2, W2>>>(conv2_w, conv2_b);
    dim3 g3(NB, K3_CHUNKS);
    netvlad_fused_kernel<<<g3, K3A_THREADS>>>(aw, ab, cent, lw, lb, out);
}

// round 17
// speedup vs baseline: 1.0486x; 1.0055x over previous
#include <cuda_runtime.h>
#include <cstdint>

// Problem dims (fixed by reference)
#define NB   32
#define H0   512
#define W0   512
#define H1   256
#define W1   256
#define HP   258            // padded H1/W1 (+1 halo each side)
#define H2   128
#define W2   128
#define MPIX (H2*W2)   // 16384
#define K3_CHUNKS 8

// Scratch (device globals: allocation-free)
// g_h1p: NHWC4 with 1-pixel zero halo. Halo is never written -> stays zero
// from static zero-init across all graph replays.
__device__ float g_h1p[(size_t)NB * HP * HP * 4];
__device__ float g_h2[(size_t)NB * MPIX * 16];     // NHWC pixel-major
__device__ float g_part[NB][K3_CHUNKS][68];        // netvlad partials
__device__ int   g_done[NB];                        // zero-init; self-resetting

// ---------------------------------------------------------------------------
// Kernel 1: conv1(3->4, 3x3 SAME) + ReLU + 2x2 avgpool, NCHW -> padded NHWC.
// Smem-staged (hoisted row pointers); 2 pooled outputs per thread; vector LDS.
// grid = (H1, NB), block = 128
// ---------------------------------------------------------------------------
#define C1_THREADS 128
__global__ void __launch_bounds__(C1_THREADS) conv1_pool_kernel(
    const float* __restrict__ x,
    const float* __restrict__ w,   // (4,3,3,3)
    const float* __restrict__ b)
{
    __shared__ float  s_in[3][4][516];
    __shared__ float4 sw4[27];
    __shared__ float  sb[4];
    const int tid = threadIdx.x;
    if (tid < 27)
        sw4[tid] = make_float4(w[tid], w[27 + tid], w[54 + tid], w[81 + tid]);
    if (tid < 4) sb[tid] = b[tid];

    const int py = blockIdx.x;
    const int n  = blockIdx.y;
    const int y0 = 2 * py - 1;

    if (tid < 12) {
        const int c = tid >> 2, r = tid & 3;
        s_in[c][r][0]   = 0.0f;
        s_in[c][r][513] = 0.0f;
        s_in[c][r][514] = 0.0f;
        s_in[c][r][515] = 0.0f;
    }

    // cooperative staging, hoisted addressing: 12 rows x 4 coalesced loads
    const float* xn = x + (size_t)n * 3 * H0 * W0;
#pragma unroll
    for (int c = 0; c < 3; ++c)
#pragma unroll
        for (int r = 0; r < 4; ++r) {
            const int y = y0 + r;
            const bool ok = ((unsigned)y < (unsigned)H0);
            const float* rowp = xn + (size_t)c * H0 * W0 + (size_t)y * W0;
            float* srow = &s_in[c][r][1];
#pragma unroll
            for (int j = 0; j < 4; ++j) {
                const int col = tid + j * C1_THREADS;
                srow[col] = ok ? __ldg(rowp + col) : 0.0f;
            }
        }
    __syncthreads();

    float a00[4], a01[4], a10[4], a11[4];
    float b00[4], b01[4], b10[4], b11[4];
#pragma unroll
    for (int co = 0; co < 4; ++co) {
        const float bb = sb[co];
        a00[co] = bb; a01[co] = bb; a10[co] = bb; a11[co] = bb;
        b00[co] = bb; b01[co] = bb; b10[co] = bb; b11[co] = bb;
    }

    const int base = 4 * tid;
#pragma unroll
    for (int c = 0; c < 3; ++c) {
        float p[4][6];
#pragma unroll
        for (int dy = 0; dy < 4; ++dy) {
            const float4 q  = *(const float4*)&s_in[c][dy][base];
            const float2 q2 = *(const float2*)&s_in[c][dy][base + 4];
            p[dy][0] = q.x;  p[dy][1] = q.y;  p[dy][2] = q.z;
            p[dy][3] = q.w;  p[dy][4] = q2.x; p[dy][5] = q2.y;
        }
#pragma unroll
        for (int ky = 0; ky < 3; ++ky)
#pragma unroll
            for (int kx = 0; kx < 3; ++kx) {
                const float4 w4 = sw4[c * 9 + ky * 3 + kx];
                const float t00 = p[ky    ][kx    ];
                const float t01 = p[ky    ][kx + 1];
                const float t10 = p[ky + 1][kx    ];
                const float t11 = p[ky + 1][kx + 1];
                const float u00 = p[ky    ][kx + 2];
                const float u01 = p[ky    ][kx + 3];
                const float u10 = p[ky + 1][kx + 2];
                const float u11 = p[ky + 1][kx + 3];
                a00[0] = fmaf(t00, w4.x, a00[0]); a00[1] = fmaf(t00, w4.y, a00[1]);
                a00[2] = fmaf(t00, w4.z, a00[2]); a00[3] = fmaf(t00, w4.w, a00[3]);
                a01[0] = fmaf(t01, w4.x, a01[0]); a01[1] = fmaf(t01, w4.y, a01[1]);
                a01[2] = fmaf(t01, w4.z, a01[2]); a01[3] = fmaf(t01, w4.w, a01[3]);
                a10[0] = fmaf(t10, w4.x, a10[0]); a10[1] = fmaf(t10, w4.y, a10[1]);
                a10[2] = fmaf(t10, w4.z, a10[2]); a10[3] = fmaf(t10, w4.w, a10[3]);
                a11[0] = fmaf(t11, w4.x, a11[0]); a11[1] = fmaf(t11, w4.y, a11[1]);
                a11[2] = fmaf(t11, w4.z, a11[2]); a11[3] = fmaf(t11, w4.w, a11[3]);
                b00[0] = fmaf(u00, w4.x, b00[0]); b00[1] = fmaf(u00, w4.y, b00[1]);
                b00[2] = fmaf(u00, w4.z, b00[2]); b00[3] = fmaf(u00, w4.w, b00[3]);
                b01[0] = fmaf(u01, w4.x, b01[0]); b01[1] = fmaf(u01, w4.y, b01[1]);
                b01[2] = fmaf(u01, w4.z, b01[2]); b01[3] = fmaf(u01, w4.w, b01[3]);
                b10[0] = fmaf(u10, w4.x, b10[0]); b10[1] = fmaf(u10, w4.y, b10[1]);
                b10[2] = fmaf(u10, w4.z, b10[2]); b10[3] = fmaf(u10, w4.w, b10[3]);
                b11[0] = fmaf(u11, w4.x, b11[0]); b11[1] = fmaf(u11, w4.y, b11[1]);
                b11[2] = fmaf(u11, w4.z, b11[2]); b11[3] = fmaf(u11, w4.w, b11[3]);
            }
    }

    float r0[4], r1[4];
#pragma unroll
    for (int co = 0; co < 4; ++co) {
        r0[co] = 0.25f * (fmaxf(a00[co], 0.f) + fmaxf(a01[co], 0.f) +
                          fmaxf(a10[co], 0.f) + fmaxf(a11[co], 0.f));
        r1[co] = 0.25f * (fmaxf(b00[co], 0.f) + fmaxf(b01[co], 0.f) +
                          fmaxf(b10[co], 0.f) + fmaxf(b11[co], 0.f));
    }
    // padded store: output (py, 2t) -> padded (py+1, 2t+1)
    float* o = g_h1p + ((size_t)n * HP * HP + (size_t)(py + 1) * HP + (2 * tid + 1)) * 4;
    ((float4*)o)[0] = make_float4(r0[0], r0[1], r0[2], r0[3]);
    ((float4*)o)[1] = make_float4(r1[0], r1[1], r1[2], r1[3]);
}

// ---------------------------------------------------------------------------
// Kernel 2: conv2 via Winograd F(2x2,3x3) + ReLU + 2x2 avgpool.
// Branch-free loads from halo-padded g_h1p. 2 co per group (float2 U).
// grid = (H2, NB), block = 128
// ---------------------------------------------------------------------------
__global__ void __launch_bounds__(W2) conv2_wino_kernel(
    const float* __restrict__ w,   // (16,4,3,3)
    const float* __restrict__ b)
{
    __shared__ float sU[16 * 4 * 16];   // [pos(16)][ci(4)][co(16)]
    __shared__ float sb[16];
    const int tid = threadIdx.x;
    if (tid < 16) sb[tid] = b[tid];

    // U = G g G^T for all (co,ci); 64 threads, one pair each
    if (tid < 64) {
        const int ci = tid >> 4, co = tid & 15;
        float g[3][3];
#pragma unroll
        for (int r = 0; r < 3; ++r)
#pragma unroll
            for (int c = 0; c < 3; ++c)
                g[r][c] = __ldg(w + co * 36 + ci * 9 + r * 3 + c);
        float T[4][3];
#pragma unroll
        for (int c = 0; c < 3; ++c) {
            T[0][c] = g[0][c];
            T[1][c] = 0.5f * (g[0][c] + g[1][c] + g[2][c]);
            T[2][c] = 0.5f * (g[0][c] - g[1][c] + g[2][c]);
            T[3][c] = g[2][c];
        }
#pragma unroll
        for (int r = 0; r < 4; ++r) {
            float U0 = T[r][0];
            float U1 = 0.5f * (T[r][0] + T[r][1] + T[r][2]);
            float U2 = 0.5f * (T[r][0] - T[r][1] + T[r][2]);
            float U3 = T[r][2];
            sU[((r * 4 + 0) * 4 + ci) * 16 + co] = U0;
            sU[((r * 4 + 1) * 4 + ci) * 16 + co] = U1;
            sU[((r * 4 + 2) * 4 + ci) * 16 + co] = U2;
            sU[((r * 4 + 3) * 4 + ci) * 16 + co] = U3;
        }
    }
    __syncthreads();

    const int px = tid;
    const int py = blockIdx.x;
    const int n  = blockIdx.y;

    // conv input rows y0+dy = 2py-1+dy -> padded rows 2py+dy; cols -> 2px+dx.
    const float* bp = g_h1p + ((size_t)n * HP * HP + (size_t)(2 * py) * HP + 2 * px) * 4;
    float p[4][4][4];  // [dy][dx][ci]
#pragma unroll
    for (int dy = 0; dy < 4; ++dy)
#pragma unroll
        for (int dx = 0; dx < 4; ++dx) {
            const float4 t = *(const float4*)(bp + ((size_t)dy * HP + dx) * 4);
            p[dy][dx][0] = t.x; p[dy][dx][1] = t.y;
            p[dy][dx][2] = t.z; p[dy][dx][3] = t.w;
        }

    // V = B^T d B per ci
    float V[4][16];   // [ci][pos]
#pragma unroll
    for (int ci = 0; ci < 4; ++ci) {
        float t[4][4];
#pragma unroll
        for (int c = 0; c < 4; ++c) {
            t[0][c] = p[0][c][ci] - p[2][c][ci];
            t[1][c] = p[1][c][ci] + p[2][c][ci];
            t[2][c] = p[2][c][ci] - p[1][c][ci];
            t[3][c] = p[1][c][ci] - p[3][c][ci];
        }
#pragma unroll
        for (int r = 0; r < 4; ++r) {
            V[ci][r * 4 + 0] = t[r][0] - t[r][2];
            V[ci][r * 4 + 1] = t[r][1] + t[r][2];
            V[ci][r * 4 + 2] = t[r][2] - t[r][1];
            V[ci][r * 4 + 3] = t[r][1] - t[r][3];
        }
    }

    // elementwise + output transform, 2 output channels at a time
    float res[16];
#pragma unroll
    for (int grp = 0; grp < 8; ++grp) {
        float Ma[16], Mb[16];
#pragma unroll
        for (int i = 0; i < 16; ++i) { Ma[i] = 0.f; Mb[i] = 0.f; }
#pragma unroll
        for (int pos = 0; pos < 16; ++pos)
#pragma unroll
            for (int ci = 0; ci < 4; ++ci) {
                const float2 u = *(const float2*)&sU[(pos * 4 + ci) * 16 + 2 * grp];
                Ma[pos] = fmaf(u.x, V[ci][pos], Ma[pos]);
                Mb[pos] = fmaf(u.y, V[ci][pos], Mb[pos]);
            }
        const float ba = sb[2 * grp], bbv = sb[2 * grp + 1];
        {
            float s0[4], s1[4];
#pragma unroll
            for (int c = 0; c < 4; ++c) {
                s0[c] = Ma[c] + Ma[4 + c] + Ma[8 + c];
                s1[c] = Ma[4 + c] - Ma[8 + c] - Ma[12 + c];
            }
            const float Y00 = s0[0] + s0[1] + s0[2];
            const float Y01 = s0[1] - s0[2] - s0[3];
            const float Y10 = s1[0] + s1[1] + s1[2];
            const float Y11 = s1[1] - s1[2] - s1[3];
            res[2 * grp] = 0.25f * (fmaxf(Y00 + ba, 0.f) + fmaxf(Y01 + ba, 0.f) +
                                    fmaxf(Y10 + ba, 0.f) + fmaxf(Y11 + ba, 0.f));
        }
        {
            float s0[4], s1[4];
#pragma unroll
            for (int c = 0; c < 4; ++c) {
                s0[c] = Mb[c] + Mb[4 + c] + Mb[8 + c];
                s1[c] = Mb[4 + c] - Mb[8 + c] - Mb[12 + c];
            }
            const float Y00 = s0[0] + s0[1] + s0[2];
            const float Y01 = s0[1] - s0[2] - s0[3];
            const float Y10 = s1[0] + s1[1] + s1[2];
            const float Y11 = s1[1] - s1[2] - s1[3];
            res[2 * grp + 1] = 0.25f * (fmaxf(Y00 + bbv, 0.f) + fmaxf(Y01 + bbv, 0.f) +
                                        fmaxf(Y10 + bbv, 0.f) + fmaxf(Y11 + bbv, 0.f));
        }
    }

    float4* o4 = (float4*)(g_h2 + ((size_t)n * MPIX + (size_t)py * W2 + px) * 16);
#pragma unroll
    for (int q = 0; q < 4; ++q)
        o4[q] = make_float4(res[q*4+0], res[q*4+1], res[q*4+2], res[q*4+3]);
}

// ---------------------------------------------------------------------------
// Kernel 3: NetVLAD partials + last-block finalize.
// grid=(NB, K3_CHUNKS), block=128. Smem-transpose reduction (no shuffle tree).
// ---------------------------------------------------------------------------
#define K3A_THREADS 128
__global__ void __launch_bounds__(K3A_THREADS) netvlad_fused_kernel(
    const float* __restrict__ aw, const float* __restrict__ ab,
    const float* __restrict__ cent,
    const float* __restrict__ lw, const float* __restrict__ lb,
    float* __restrict__ out)
{
    const int n   = blockIdx.x;
    const int ch  = blockIdx.y;
    const int tid = threadIdx.x;

    __shared__ float s_aw[64];
    __shared__ float s_ab[4];
    __shared__ float sred[K3A_THREADS][69];   // [thread][slot], pad 69
    if (tid < 64) s_aw[tid] = aw[tid];
    if (tid < 4)  s_ab[tid] = ab[tid];
    __syncthreads();

    float acc[68];
#pragma unroll
    for (int i = 0; i < 68; ++i) acc[i] = 0.0f;

    const int m0 = ch * (MPIX / K3_CHUNKS);
    const int m1 = m0 + (MPIX / K3_CHUNKS);
    const float* base = g_h2 + (size_t)n * MPIX * 16;
    for (int m = m0 + tid; m < m1; m += K3A_THREADS) {
        const float4* xp = (const float4*)(base + (size_t)m * 16);
        float xv[16];
#pragma unroll
        for (int q = 0; q < 4; ++q) {
            float4 v = xp[q];
            xv[q*4+0] = v.x; xv[q*4+1] = v.y; xv[q*4+2] = v.z; xv[q*4+3] = v.w;
        }
        float lg[4];
#pragma unroll
        for (int k = 0; k < 4; ++k) {
            float sres = s_ab[k];
#pragma unroll
            for (int c = 0; c < 16; ++c) sres = fmaf(xv[c], s_aw[k * 16 + c], sres);
            lg[k] = sres;
        }
        const float mx = fmaxf(fmaxf(lg[0], lg[1]), fmaxf(lg[2], lg[3]));
        float e[4], es = 0.0f;
#pragma unroll
        for (int k = 0; k < 4; ++k) { e[k] = __expf(lg[k] - mx); es += e[k]; }
        const float inv = __fdividef(1.0f, es);
#pragma unroll
        for (int k = 0; k < 4; ++k) {
            const float a = e[k] * inv;
            acc[64 + k] += a;
#pragma unroll
            for (int c = 0; c < 16; ++c)
                acc[k * 16 + c] = fmaf(a, xv[c], acc[k * 16 + c]);
        }
    }

    // transpose reduction: each thread dumps its 68 accs, 68 threads column-sum
#pragma unroll
    for (int i = 0; i < 68; ++i) sred[tid][i] = acc[i];
    __syncthreads();
    if (tid < 68) {
        float s0 = 0.f, s1 = 0.f, s2 = 0.f, s3 = 0.f;
#pragma unroll 8
        for (int q = 0; q < K3A_THREADS; q += 4) {
            s0 += sred[q    ][tid];
            s1 += sred[q + 1][tid];
            s2 += sred[q + 2][tid];
            s3 += sred[q + 3][tid];
        }
        g_part[n][ch][tid] = (s0 + s1) + (s2 + s3);
    }

    // ---- last-block-per-image finalize (store -> fence -> sync -> atomic) --
    __threadfence();
    __syncthreads();
    __shared__ int s_last;
    if (tid == 0) {
        const int old = atomicAdd(&g_done[n], 1);
        s_last = (old == K3_CHUNKS - 1) ? 1 : 0;
    }
    __syncthreads();
    if (!s_last) return;

    __shared__ float sv[68];
    if (tid < 68) {
        float sres = 0.0f;
#pragma unroll
        for (int cc = 0; cc < K3_CHUNKS; ++cc) sres += __ldcg(&g_part[n][cc][tid]);
        sv[tid] = sres;
    }
    __syncthreads();

    __shared__ float v2[64];
    __shared__ float nk[4];
    __shared__ float gn;
    if (tid < 64) {
        const int k = tid >> 4;
        v2[tid] = sv[tid] - sv[64 + k] * __ldg(cent + tid);
    }
    __syncthreads();
    if (tid < 4) {
        float sres = 0.0f;
#pragma unroll
        for (int c = 0; c < 16; ++c) { const float v = v2[tid * 16 + c]; sres = fmaf(v, v, sres); }
        nk[tid] = fmaxf(sqrtf(sres), 1e-12f);
    }
    __syncthreads();
    if (tid < 64) v2[tid] = v2[tid] / nk[tid >> 4];
    __syncthreads();
    if (tid == 0) {
        float sres = 0.0f;
#pragma unroll
        for (int i = 0; i < 64; ++i) sres = fmaf(v2[i], v2[i], sres);
        gn = fmaxf(sqrtf(sres), 1e-12f);
        g_done[n] = 0;   // reset for next graph replay
    }
    __syncthreads();
    if (tid < 7) {
        float sres = __ldg(lb + tid);
        const float ig = 1.0f / gn;
#pragma unroll
        for (int i = 0; i < 64; ++i)
            sres = fmaf(v2[i] * ig, __ldg(lw + tid * 64 + i), sres);
        out[n * 7 + tid] = sres;
    }
}

// ---------------------------------------------------------------------------
extern "C" void kernel_launch(void* const* d_in, const int* in_sizes, int n_in,
                              void* d_out, int out_size)
{
    (void)in_sizes; (void)n_in; (void)out_size;
    const float* x       = (const float*)d_in[0];
    const float* conv1_w = (const float*)d_in[1];
    const float* conv1_b = (const float*)d_in[2];
    const float* conv2_w = (const float*)d_in[3];
    const float* conv2_b = (const float*)d_in[4];
    const float* cent    = (const float*)d_in[5];
    const float* aw      = (const float*)d_in[6];
    const float* ab      = (const float*)d_in[7];
    const float* lw      = (const float*)d_in[8];
    const float* lb      = (const float*)d_in[9];
    float* out = (float*)d_out;

    dim3 g1(H1, NB); conv1_pool_kernel<<<g1, C1_THREADS>>>(x, conv1_w, conv1_b);
    dim3 g2(H2, NB); conv2_wino_kernel<<<g2, W2>>>(conv2_w, conv2_b);
    dim3 g3(NB, K3_CHUNKS);
    netvlad_fused_kernel<<<g3, K3A_THREADS>>>(aw, ab, cent, lw, lb, out);
}